// round 15
// baseline (speedup 1.0000x reference)
#include <cuda_runtime.h>
#include <cuda_bf16.h>
#include <cstdint>

// ---------------------------------------------------------------------------
// Problem constants
// ---------------------------------------------------------------------------
#define B_ROWS   16384
#define D_DIM    2048
#define L_LAYERS 3
#define E_EXP    8
#define NCOL     (L_LAYERS * 1024)   // 3072 interleaved U/V columns (all layers)
#define NEXP     (L_LAYERS * E_EXP)  // 24

// Phase-fused GEMM tiling: 128x128 tile, 4 warps (2m x 2n), 64x64 warp tile.
// K chunk = 32 bf16 (64 B rows). Per chunk: load Ahi/Alo/Bhi/Blo pages once,
// run hh, hl, lh MMA sub-passes with fragment reuse. 3 stages, 2 CTAs/SM.
#define BM 128
#define BN 128
#define KB2 32                        // bf16 per chunk (64 B rows)
#define ROWB 64                       // bytes per row in smem page
#define STAGES 3
#define NCHUNK (D_DIM / KB2)          // 64
#define PAGE_BYTES (BM * ROWB)        // 8 KB
#define STAGE_BYTES (4 * PAGE_BYTES)  // 32 KB (Ahi, Alo, Bhi, Blo)
#define AHI_OFF 0u
#define ALO_OFF (1u * PAGE_BYTES)
#define BHI_OFF (2u * PAGE_BYTES)
#define BLO_OFF (3u * PAGE_BYTES)
#define SMEM_TOTAL (STAGES * STAGE_BYTES)    // 96 KB -> 2 CTAs/SM

// Gate K-split
#define GK_SPLIT 4
#define GK_LEN   (D_DIM / GK_SPLIT)   // 512

// ---------------------------------------------------------------------------
// Device scratch (static)
// ---------------------------------------------------------------------------
__device__ __nv_bfloat16 g_Ahi[(size_t)B_ROWS * D_DIM];
__device__ __nv_bfloat16 g_Alo[(size_t)B_ROWS * D_DIM];
__device__ __nv_bfloat16 g_Bhi[(size_t)NCOL * D_DIM];
__device__ __nv_bfloat16 g_Blo[(size_t)NCOL * D_DIM];
__device__ float         g_e0[(size_t)B_ROWS * NEXP];
__device__ float         g_logit_part[(size_t)GK_SPLIT * B_ROWS * NEXP];

// ---------------------------------------------------------------------------
// Helpers
// ---------------------------------------------------------------------------
__device__ __forceinline__ uint32_t smem_u32(const void* p) {
    uint32_t a;
    asm("{ .reg .u64 t; cvta.to.shared.u64 t, %1; cvt.u32.u64 %0, t; }"
        : "=r"(a) : "l"(p));
    return a;
}
__device__ __forceinline__ uint32_t swz64(uint32_t off) {      // SW64
    return off ^ ((off >> 3) & 0x30);
}
__device__ __forceinline__ void cpa16(uint32_t dst, const void* src) {
    asm volatile("cp.async.cg.shared.global [%0], [%1], 16;"
                 :: "r"(dst), "l"(src) : "memory");
}
__device__ __forceinline__ void cpa_commit() {
    asm volatile("cp.async.commit_group;" ::: "memory");
}
__device__ __forceinline__ void cpa_wait1() {
    asm volatile("cp.async.wait_group 1;" ::: "memory");
}
__device__ __forceinline__ void ldsm_x4(uint32_t* r, uint32_t addr) {
    asm volatile("ldmatrix.sync.aligned.m8n8.x4.shared.b16 {%0,%1,%2,%3}, [%4];"
                 : "=r"(r[0]), "=r"(r[1]), "=r"(r[2]), "=r"(r[3]) : "r"(addr));
}
__device__ __forceinline__ void mma16816(float* d, const uint32_t* a,
                                         uint32_t b0, uint32_t b1) {
    asm volatile(
        "mma.sync.aligned.m16n8k16.row.col.f32.bf16.bf16.f32 "
        "{%0,%1,%2,%3}, {%4,%5,%6,%7}, {%8,%9}, {%0,%1,%2,%3};"
        : "+f"(d[0]), "+f"(d[1]), "+f"(d[2]), "+f"(d[3])
        : "r"(a[0]), "r"(a[1]), "r"(a[2]), "r"(a[3]), "r"(b0), "r"(b1));
}

// split 8 consecutive floats -> uint4 of hi bf16 + uint4 of lo bf16
__device__ __forceinline__ void split8(const float* src,
                                       __nv_bfloat16* dhi, __nv_bfloat16* dlo)
{
    float4 a = *reinterpret_cast<const float4*>(src);
    float4 b = *reinterpret_cast<const float4*>(src + 4);
    float v[8] = {a.x, a.y, a.z, a.w, b.x, b.y, b.z, b.w};
    __nv_bfloat16 hi[8], lo[8];
#pragma unroll
    for (int j = 0; j < 8; j++) {
        hi[j] = __float2bfloat16(v[j]);
        lo[j] = __float2bfloat16(v[j] - __bfloat162float(hi[j]));
    }
    *reinterpret_cast<uint4*>(dhi) = *reinterpret_cast<uint4*>(hi);
    *reinterpret_cast<uint4*>(dlo) = *reinterpret_cast<uint4*>(lo);
}

// ---------------------------------------------------------------------------
// Merged prep (R14, unchanged): three disjoint block ranges.
// ---------------------------------------------------------------------------
#define GL_BM 128
#define GL_BK 32
#define PREP_GATE   (128 * GK_SPLIT)              // 512
#define PREP_WB     (PREP_GATE + NCOL)            // 3584
#define PREP_TOTAL  (PREP_WB + 8192)              // 11776

__global__ __launch_bounds__(256) void prep_all(
    const float* __restrict__ U, const float* __restrict__ V,
    const float* __restrict__ X0, const float* __restrict__ Wg)
{
    const int tid = threadIdx.x;

    if (blockIdx.x >= PREP_WB) {
        const size_t base =
            (((size_t)(blockIdx.x - PREP_WB)) * 256 + tid) * 16;
#pragma unroll
        for (int g = 0; g < 2; g++) {
            const size_t idx = base + g * 8;
            split8(X0 + idx, &g_Ahi[idx], &g_Alo[idx]);
        }
        return;
    }

    if (blockIdx.x >= PREP_GATE) {
        const int row = blockIdx.x - PREP_GATE;
        const int l = row >> 10, c = row & 1023;
        const int e = c >> 7, i = c & 127, r = i >> 1, uv = i & 1;
        const float* src = (uv ? V : U)
                         + (((size_t)(l * E_EXP + e)) * 64 + r) * D_DIM;
        const size_t dst = (size_t)row * D_DIM + tid * 8;
        split8(src + tid * 8, &g_Bhi[dst], &g_Blo[dst]);
        return;
    }

    // ---- gate logit partials: block = (m-block, K-chunk) ----
    __shared__ float As[GL_BK][GL_BM + 1];
    __shared__ float Ws[GL_BK][36];
    const int mblk = blockIdx.x >> 2;
    const int kchunk = blockIdx.x & 3;
    const int m0 = mblk * GL_BM;
    const int kbeg = kchunk * GK_LEN;
    const int row = tid >> 1;
    const int ch = (tid & 1) * 12;
    float acc[12];
#pragma unroll
    for (int j = 0; j < 12; j++) acc[j] = 0.f;

    for (int kc = kbeg; kc < kbeg + GK_LEN; kc += GL_BK) {
#pragma unroll
        for (int i = 0; i < 4; i++) {
            const int idx = i * 256 + tid;
            const int r = idx >> 3, c4 = (idx & 7) * 4;
            float4 v = *reinterpret_cast<const float4*>(
                X0 + (size_t)(m0 + r) * D_DIM + kc + c4);
            As[c4 + 0][r] = v.x; As[c4 + 1][r] = v.y;
            As[c4 + 2][r] = v.z; As[c4 + 3][r] = v.w;
        }
        if (tid < 192) {
            const int r = tid >> 3, c4 = (tid & 7) * 4;
            float4 v = *reinterpret_cast<const float4*>(
                Wg + (size_t)r * D_DIM + kc + c4);
            Ws[c4 + 0][r] = v.x; Ws[c4 + 1][r] = v.y;
            Ws[c4 + 2][r] = v.z; Ws[c4 + 3][r] = v.w;
        }
        __syncthreads();
#pragma unroll 8
        for (int kk = 0; kk < GL_BK; kk++) {
            const float a = As[kk][row];
            float4 w0 = *reinterpret_cast<float4*>(&Ws[kk][ch]);
            float4 w1 = *reinterpret_cast<float4*>(&Ws[kk][ch + 4]);
            float4 w2 = *reinterpret_cast<float4*>(&Ws[kk][ch + 8]);
            acc[0] += a * w0.x; acc[1] += a * w0.y;
            acc[2] += a * w0.z; acc[3] += a * w0.w;
            acc[4] += a * w1.x; acc[5] += a * w1.y;
            acc[6] += a * w1.z; acc[7] += a * w1.w;
            acc[8] += a * w2.x; acc[9] += a * w2.y;
            acc[10] += a * w2.z; acc[11] += a * w2.w;
        }
        __syncthreads();
    }
    float* dst = g_logit_part + ((size_t)kchunk * B_ROWS + m0 + row) * NEXP + ch;
#pragma unroll
    for (int j = 0; j < 12; j++) dst[j] = acc[j];
}

// ---------------------------------------------------------------------------
// Phase-fused HMMA GEMM, 2 CTAs/SM.
// Grid (24 experts, 128 m-tiles). 128 threads = 4 warps (2m x 2n).
// Per 32-K chunk: cp.async all 4 pages once; per k16: ldsm ahi,bhi -> hh;
// ldsm blo -> hl (reuse ahi); ldsm alo -> lh (reuse bhi).
// ---------------------------------------------------------------------------
__global__ __launch_bounds__(128, 2) void gemm_hmma()
{
    extern __shared__ char smem[];
    const uint32_t sb = smem_u32(smem);
    const int tid = threadIdx.x;
    const int lane = tid & 31, warp = tid >> 5;
    const int wm = warp & 1, wn = warp >> 1;     // 2m x 2n
    const int nt = blockIdx.x;                    // 0..23 (global expert)
    const int m0 = blockIdx.y * BM;
    const size_t brow0 = (size_t)nt * BN;

    float acc[4][8][4];
#pragma unroll
    for (int mi = 0; mi < 4; mi++)
#pragma unroll
        for (int ni = 0; ni < 8; ni++)
#pragma unroll
            for (int j = 0; j < 4; j++) acc[mi][ni][j] = 0.f;

    auto load_stage = [&](int chunk) {
        if (chunk < NCHUNK) {
            const int k0 = chunk * KB2;
            const uint32_t st = sb + (chunk % STAGES) * STAGE_BYTES;
            // each page: 128 rows x 64 B = 512 x 16B chunks, 4 per thread
#pragma unroll
            for (int i = 0; i < 4; i++) {
                const int idx = i * 128 + tid;
                const int r = idx >> 2, c = idx & 3;
                const uint32_t soff = swz64(r * ROWB + c * 16);
                const size_t ga = (size_t)(m0 + r) * D_DIM + k0 + c * 8;
                const size_t gb = (brow0 + r) * D_DIM + k0 + c * 8;
                cpa16(st + AHI_OFF + soff, g_Ahi + ga);
                cpa16(st + ALO_OFF + soff, g_Alo + ga);
                cpa16(st + BHI_OFF + soff, g_Bhi + gb);
                cpa16(st + BLO_OFF + soff, g_Blo + gb);
            }
        }
        cpa_commit();
    };

    load_stage(0); load_stage(1);

    const int arow = wm * 64 + (lane & 15);
    const int brow = wn * 64 + (lane & 15);
    const int khalf = (lane >> 4) * 16;           // byte offset within row

    for (int chunk = 0; chunk < NCHUNK; ++chunk) {
        cpa_wait1();
        __syncthreads();
        load_stage(chunk + 2);

        const uint32_t st = sb + (chunk % STAGES) * STAGE_BYTES;
#pragma unroll
        for (int k16 = 0; k16 < 2; k16++) {
            const int kb = k16 * 32 + khalf;      // 0,16,32,48
            uint32_t ahi[4][4], bhi[4][4], t[4][4];
#pragma unroll
            for (int mi = 0; mi < 4; mi++)
                ldsm_x4(ahi[mi], st + AHI_OFF + swz64((arow + mi * 16) * ROWB + kb));
#pragma unroll
            for (int nj = 0; nj < 4; nj++)
                ldsm_x4(bhi[nj], st + BHI_OFF + swz64((brow + nj * 16) * ROWB + kb));
            // hh
#pragma unroll
            for (int mi = 0; mi < 4; mi++)
#pragma unroll
                for (int ni = 0; ni < 8; ni++)
                    mma16816(acc[mi][ni], ahi[mi],
                             bhi[ni >> 1][ni & 1], bhi[ni >> 1][(ni & 1) + 2]);
            // hl: ahi x blo
#pragma unroll
            for (int nj = 0; nj < 4; nj++)
                ldsm_x4(t[nj], st + BLO_OFF + swz64((brow + nj * 16) * ROWB + kb));
#pragma unroll
            for (int mi = 0; mi < 4; mi++)
#pragma unroll
                for (int ni = 0; ni < 8; ni++)
                    mma16816(acc[mi][ni], ahi[mi],
                             t[ni >> 1][ni & 1], t[ni >> 1][(ni & 1) + 2]);
            // lh: alo x bhi (reuse t for alo)
#pragma unroll
            for (int mi = 0; mi < 4; mi++)
                ldsm_x4(t[mi], st + ALO_OFF + swz64((arow + mi * 16) * ROWB + kb));
#pragma unroll
            for (int mi = 0; mi < 4; mi++)
#pragma unroll
                for (int ni = 0; ni < 8; ni++)
                    mma16816(acc[mi][ni], t[mi],
                             bhi[ni >> 1][ni & 1], bhi[ni >> 1][(ni & 1) + 2]);
        }
    }

    // ---- Fused epilogue: pair products -> per-row expert sum ----
    __syncthreads();
    float* esum = reinterpret_cast<float*>(smem);   // [128]
    esum[tid] = 0.f;
    __syncthreads();

#pragma unroll
    for (int mi = 0; mi < 4; mi++) {
        float pl = 0.f, ph = 0.f;
#pragma unroll
        for (int ni = 0; ni < 8; ni++) {
            pl += acc[mi][ni][0] * acc[mi][ni][1];
            ph += acc[mi][ni][2] * acc[mi][ni][3];
        }
        pl += __shfl_xor_sync(0xffffffffu, pl, 1);
        pl += __shfl_xor_sync(0xffffffffu, pl, 2);
        ph += __shfl_xor_sync(0xffffffffu, ph, 1);
        ph += __shfl_xor_sync(0xffffffffu, ph, 2);
        if ((lane & 3) == 0) {
            const int r = wm * 64 + mi * 16 + (lane >> 2);
            atomicAdd(&esum[r], pl);
            atomicAdd(&esum[r + 8], ph);
        }
    }
    __syncthreads();
    g_e0[(size_t)(m0 + tid) * NEXP + nt] = esum[tid];
}

// ---------------------------------------------------------------------------
// Fused finalize (R14, unchanged).
// ---------------------------------------------------------------------------
__global__ __launch_bounds__(256) void finalize(
    const float* __restrict__ X0, const float* __restrict__ bg,
    float* __restrict__ out)
{
    __shared__ float sc[4];
    const int t = threadIdx.x;
    const int b0 = blockIdx.x * 4;

    if (t < 4) {
        const int b = b0 + t;
        const float* e0 = g_e0 + (size_t)b * NEXP;
        float lg[NEXP];
#pragma unroll
        for (int e = 0; e < NEXP; e++) {
            float s = 0.f;
#pragma unroll
            for (int p = 0; p < GK_SPLIT; p++)
                s += g_logit_part[((size_t)p * B_ROWS + b) * NEXP + e];
            lg[e] = s;
        }
        float c = 1.f;
#pragma unroll
        for (int l = 0; l < L_LAYERS; l++) {
            const int base = l * E_EXP;
            float logit[E_EXP], mx = -1e30f;
#pragma unroll
            for (int e = 0; e < E_EXP; e++) {
                logit[e] = c * lg[base + e] + bg[base + e];
                mx = fmaxf(mx, logit[e]);
            }
            float se = 0.f, acc = 0.f;
#pragma unroll
            for (int e = 0; e < E_EXP; e++) {
                const float ge = expf(logit[e] - mx);
                se += ge;
                acc += ge * e0[base + e];
            }
            c += c * c * (acc / se);
        }
        sc[t] = c;
    }
    __syncthreads();

    const size_t base4 = (size_t)b0 * (D_DIM / 4);
    const float4* x4 = reinterpret_cast<const float4*>(X0) + base4;
    float4* o4 = reinterpret_cast<float4*>(out) + base4;
#pragma unroll
    for (int i = 0; i < 8; i++) {
        const int j = i * 256 + t;
        const float c = sc[j >> 9];
        float4 x = x4[j];
        x.x *= c; x.y *= c; x.z *= c; x.w *= c;
        o4[j] = x;
    }
}

// ---------------------------------------------------------------------------
// Launch: 3 kernels total.
// ---------------------------------------------------------------------------
extern "C" void kernel_launch(void* const* d_in, const int* in_sizes, int n_in,
                              void* d_out, int out_size) {
    const float* X0 = (const float*)d_in[0];
    const float* U  = (const float*)d_in[1];
    const float* V  = (const float*)d_in[2];
    const float* Wg = (const float*)d_in[3];
    const float* bg = (const float*)d_in[4];
    float* out = (float*)d_out;

    cudaFuncSetAttribute(gemm_hmma, cudaFuncAttributeMaxDynamicSharedMemorySize,
                         SMEM_TOTAL);

    prep_all<<<PREP_TOTAL, 256>>>(U, V, X0, Wg);
    gemm_hmma<<<dim3(NEXP, B_ROWS / BM), 128, SMEM_TOTAL>>>();
    finalize<<<B_ROWS / 4, 256>>>(X0, bg, out);
}

// round 16
// speedup vs baseline: 1.0013x; 1.0013x over previous
#include <cuda_runtime.h>
#include <cuda_bf16.h>
#include <cstdint>

// ---------------------------------------------------------------------------
// Problem constants
// ---------------------------------------------------------------------------
#define B_ROWS   16384
#define D_DIM    2048
#define L_LAYERS 3
#define E_EXP    8
#define NCOL     (L_LAYERS * 1024)   // 3072 interleaved U/V columns (all layers)
#define NEXP     (L_LAYERS * E_EXP)  // 24

// GEMM tiling (R5/R14 config): 128x128 tile, 4 warps (2m x 2n), 64x64 warp
// tile, 3 stages, 2 CTAs/SM.
#define BM 128
#define BN 128
#define KB 64                         // bf16 per k-step (128 B rows)
#define STAGES 3
#define KSTEPS (D_DIM / KB)           // 32
#define NSTEPS (3 * KSTEPS)           // 96: phases hh, lh, hl
#define A_BYTES (BM * 128)            // 16 KB
#define B_BYTES (BN * 128)            // 16 KB
#define STAGE_BYTES (A_BYTES + B_BYTES)      // 32 KB
#define SMEM_TOTAL (STAGES * STAGE_BYTES)    // 96 KB -> 2 CTAs/SM

// Gate K-split (runs inside the GEMM launch, blockIdx.x in [24, 28))
#define GK_SPLIT 4
#define GK_LEN   (D_DIM / GK_SPLIT)   // 512
#define GL_BK 32

// ---------------------------------------------------------------------------
// Device scratch (static)
// ---------------------------------------------------------------------------
__device__ __nv_bfloat16 g_Ahi[(size_t)B_ROWS * D_DIM];
__device__ __nv_bfloat16 g_Alo[(size_t)B_ROWS * D_DIM];
__device__ __nv_bfloat16 g_Bhi[(size_t)NCOL * D_DIM];
__device__ __nv_bfloat16 g_Blo[(size_t)NCOL * D_DIM];
__device__ float         g_e0[(size_t)B_ROWS * NEXP];
__device__ float         g_logit_part[(size_t)GK_SPLIT * B_ROWS * NEXP];

// ---------------------------------------------------------------------------
// Helpers
// ---------------------------------------------------------------------------
__device__ __forceinline__ uint32_t smem_u32(const void* p) {
    uint32_t a;
    asm("{ .reg .u64 t; cvta.to.shared.u64 t, %1; cvt.u32.u64 %0, t; }"
        : "=r"(a) : "l"(p));
    return a;
}
__device__ __forceinline__ uint32_t swz(uint32_t off) {        // SW128
    return off ^ ((off >> 3) & 0x70);
}
__device__ __forceinline__ void cpa16(uint32_t dst, const void* src) {
    asm volatile("cp.async.cg.shared.global [%0], [%1], 16;"
                 :: "r"(dst), "l"(src) : "memory");
}
__device__ __forceinline__ void cpa_commit() {
    asm volatile("cp.async.commit_group;" ::: "memory");
}
__device__ __forceinline__ void cpa_wait1() {
    asm volatile("cp.async.wait_group 1;" ::: "memory");
}
__device__ __forceinline__ void ldsm_x4(uint32_t* r, uint32_t addr) {
    asm volatile("ldmatrix.sync.aligned.m8n8.x4.shared.b16 {%0,%1,%2,%3}, [%4];"
                 : "=r"(r[0]), "=r"(r[1]), "=r"(r[2]), "=r"(r[3]) : "r"(addr));
}
__device__ __forceinline__ void mma16816(float* d, const uint32_t* a,
                                         uint32_t b0, uint32_t b1) {
    asm volatile(
        "mma.sync.aligned.m16n8k16.row.col.f32.bf16.bf16.f32 "
        "{%0,%1,%2,%3}, {%4,%5,%6,%7}, {%8,%9}, {%0,%1,%2,%3};"
        : "+f"(d[0]), "+f"(d[1]), "+f"(d[2]), "+f"(d[3])
        : "r"(a[0]), "r"(a[1]), "r"(a[2]), "r"(a[3]), "r"(b0), "r"(b1));
}

// split 8 consecutive floats -> uint4 of hi bf16 + uint4 of lo bf16
__device__ __forceinline__ void split8(const float* src,
                                       __nv_bfloat16* dhi, __nv_bfloat16* dlo)
{
    float4 a = *reinterpret_cast<const float4*>(src);
    float4 b = *reinterpret_cast<const float4*>(src + 4);
    float v[8] = {a.x, a.y, a.z, a.w, b.x, b.y, b.z, b.w};
    __nv_bfloat16 hi[8], lo[8];
#pragma unroll
    for (int j = 0; j < 8; j++) {
        hi[j] = __float2bfloat16(v[j]);
        lo[j] = __float2bfloat16(v[j] - __bfloat162float(hi[j]));
    }
    *reinterpret_cast<uint4*>(dhi) = *reinterpret_cast<uint4*>(hi);
    *reinterpret_cast<uint4*>(dlo) = *reinterpret_cast<uint4*>(lo);
}

// ---------------------------------------------------------------------------
// Streaming prep: splits only (weights + X0). Pure DRAM streaming.
//   [0, NCOL)        : weight split
//   [NCOL, NCOL+8192): X0 hi/lo split
// ---------------------------------------------------------------------------
#define PREP_TOTAL (NCOL + 8192)

__global__ __launch_bounds__(256) void prep_stream(
    const float* __restrict__ U, const float* __restrict__ V,
    const float* __restrict__ X0)
{
    const int tid = threadIdx.x;

    if (blockIdx.x >= NCOL) {
        const size_t base = (((size_t)(blockIdx.x - NCOL)) * 256 + tid) * 16;
#pragma unroll
        for (int g = 0; g < 2; g++) {
            const size_t idx = base + g * 8;
            split8(X0 + idx, &g_Ahi[idx], &g_Alo[idx]);
        }
        return;
    }

    const int row = blockIdx.x;
    const int l = row >> 10, c = row & 1023;
    const int e = c >> 7, i = c & 127, r = i >> 1, uv = i & 1;
    const float* src = (uv ? V : U)
                     + (((size_t)(l * E_EXP + e)) * 64 + r) * D_DIM;
    const size_t dst = (size_t)row * D_DIM + tid * 8;
    split8(src + tid * 8, &g_Bhi[dst], &g_Blo[dst]);
}

// ---------------------------------------------------------------------------
// HMMA GEMM + embedded gate-logit blocks.
// Grid (28, 128), 128 threads:
//   blockIdx.x < 24 : R14 HMMA GEMM body (expert nt = blockIdx.x)
//   blockIdx.x >= 24: gate logit partial (kchunk = x-24, mblk = blockIdx.y)
//     -> fp32 FMA work that hides in the GEMM's idle fma pipe.
// ---------------------------------------------------------------------------
__global__ __launch_bounds__(128, 2) void gemm_hmma(
    const float* __restrict__ X0, const float* __restrict__ Wg)
{
    extern __shared__ char smem[];
    const uint32_t sb = smem_u32(smem);
    const int tid = threadIdx.x;

    if (blockIdx.x >= NEXP) {
        // ---- gate logit partial: 128 threads, 1 thread per m-row ----
        // smem layout inside dynamic smem: As[32][129] then Ws[32][36]
        float (*As)[129] = reinterpret_cast<float (*)[129]>(smem);
        float (*Ws)[36] = reinterpret_cast<float (*)[36]>(smem + 32 * 129 * 4);
        const int kchunk = blockIdx.x - NEXP;       // 0..3
        const int m0 = blockIdx.y * 128;
        const int kbeg = kchunk * GK_LEN;
        float acc[NEXP];
#pragma unroll
        for (int j = 0; j < NEXP; j++) acc[j] = 0.f;

        for (int kc = kbeg; kc < kbeg + GK_LEN; kc += GL_BK) {
            // X0 tile: 128 rows x 32 k = 1024 float4, 8 per thread
#pragma unroll
            for (int i = 0; i < 8; i++) {
                const int idx = i * 128 + tid;
                const int r = idx >> 3, c4 = (idx & 7) * 4;
                float4 v = *reinterpret_cast<const float4*>(
                    X0 + (size_t)(m0 + r) * D_DIM + kc + c4);
                As[c4 + 0][r] = v.x; As[c4 + 1][r] = v.y;
                As[c4 + 2][r] = v.z; As[c4 + 3][r] = v.w;
            }
            // Wg tile: 24 rows x 32 k = 192 float4
#pragma unroll
            for (int i = 0; i < 2; i++) {
                const int idx = i * 128 + tid;
                if (idx < 192) {
                    const int r = idx >> 3, c4 = (idx & 7) * 4;
                    float4 v = *reinterpret_cast<const float4*>(
                        Wg + (size_t)r * D_DIM + kc + c4);
                    Ws[c4 + 0][r] = v.x; Ws[c4 + 1][r] = v.y;
                    Ws[c4 + 2][r] = v.z; Ws[c4 + 3][r] = v.w;
                }
            }
            __syncthreads();
#pragma unroll 4
            for (int kk = 0; kk < GL_BK; kk++) {
                const float a = As[kk][tid];
#pragma unroll
                for (int j = 0; j < NEXP; j++)
                    acc[j] += a * Ws[kk][j];
            }
            __syncthreads();
        }
        float* dst = g_logit_part
                   + ((size_t)kchunk * B_ROWS + m0 + tid) * NEXP;
#pragma unroll
        for (int j = 0; j < NEXP; j++) dst[j] = acc[j];
        return;
    }

    // ---- HMMA GEMM body (R14 verbatim) ----
    const int lane = tid & 31, warp = tid >> 5;
    const int wm = warp & 1, wn = warp >> 1;     // 2m x 2n
    const int nt = blockIdx.x;                    // 0..23 (global expert)
    const int m0 = blockIdx.y * BM;
    const size_t brow0 = (size_t)nt * BN;

    float acc[4][8][4];
#pragma unroll
    for (int mi = 0; mi < 4; mi++)
#pragma unroll
        for (int ni = 0; ni < 8; ni++)
#pragma unroll
            for (int j = 0; j < 4; j++) acc[mi][ni][j] = 0.f;

    auto load_stage = [&](int step) {
        if (step < NSTEPS) {
            const int p = (step >= 2 * KSTEPS) ? 2 : (step >= KSTEPS ? 1 : 0);
            const int k0 = (step - p * KSTEPS) * KB;
            const __nv_bfloat16* Asrc = (p == 1) ? g_Alo : g_Ahi;
            const __nv_bfloat16* Bsrc = (p == 2) ? g_Blo : g_Bhi;
            const uint32_t a_base = sb + (step % STAGES) * STAGE_BYTES;
            const uint32_t b_base = a_base + A_BYTES;
#pragma unroll
            for (int i = 0; i < 8; i++) {
                const int idx = i * 128 + tid;
                const int r = idx >> 3, c = idx & 7;
                cpa16(a_base + swz(r * 128 + c * 16),
                      Asrc + (size_t)(m0 + r) * D_DIM + k0 + c * 8);
            }
#pragma unroll
            for (int i = 0; i < 8; i++) {
                const int idx = i * 128 + tid;
                const int r = idx >> 3, c = idx & 7;
                cpa16(b_base + swz(r * 128 + c * 16),
                      Bsrc + (brow0 + r) * D_DIM + k0 + c * 8);
            }
        }
        cpa_commit();
    };

    load_stage(0); load_stage(1);

    const int arow = wm * 64 + (lane & 15);
    const int brow = wn * 64 + (lane & 15);
    const int khalf = (lane >> 4) * 16;

    for (int step = 0; step < NSTEPS; ++step) {
        cpa_wait1();
        __syncthreads();
        load_stage(step + 2);

        const uint32_t a_base = sb + (step % STAGES) * STAGE_BYTES;
        const uint32_t b_base = a_base + A_BYTES;
#pragma unroll
        for (int k16 = 0; k16 < 4; k16++) {
            const int kb = k16 * 32 + khalf;
            uint32_t a[4][4], bb[4][4];
#pragma unroll
            for (int mi = 0; mi < 4; mi++)
                ldsm_x4(a[mi], a_base + swz((arow + mi * 16) * 128 + kb));
#pragma unroll
            for (int nj = 0; nj < 4; nj++)
                ldsm_x4(bb[nj], b_base + swz((brow + nj * 16) * 128 + kb));
#pragma unroll
            for (int mi = 0; mi < 4; mi++)
#pragma unroll
                for (int ni = 0; ni < 8; ni++)
                    mma16816(acc[mi][ni], a[mi],
                             bb[ni >> 1][ni & 1], bb[ni >> 1][(ni & 1) + 2]);
        }
    }

    // ---- Fused epilogue: pair products -> per-row expert sum ----
    __syncthreads();
    float* esum = reinterpret_cast<float*>(smem);   // [128]
    esum[tid] = 0.f;
    __syncthreads();

#pragma unroll
    for (int mi = 0; mi < 4; mi++) {
        float pl = 0.f, ph = 0.f;
#pragma unroll
        for (int ni = 0; ni < 8; ni++) {
            pl += acc[mi][ni][0] * acc[mi][ni][1];
            ph += acc[mi][ni][2] * acc[mi][ni][3];
        }
        pl += __shfl_xor_sync(0xffffffffu, pl, 1);
        pl += __shfl_xor_sync(0xffffffffu, pl, 2);
        ph += __shfl_xor_sync(0xffffffffu, ph, 1);
        ph += __shfl_xor_sync(0xffffffffu, ph, 2);
        if ((lane & 3) == 0) {
            const int r = wm * 64 + mi * 16 + (lane >> 2);
            atomicAdd(&esum[r], pl);
            atomicAdd(&esum[r + 8], ph);
        }
    }
    __syncthreads();
    g_e0[(size_t)(m0 + tid) * NEXP + nt] = esum[tid];
}

// ---------------------------------------------------------------------------
// Fused finalize (R14, unchanged).
// ---------------------------------------------------------------------------
__global__ __launch_bounds__(256) void finalize(
    const float* __restrict__ X0, const float* __restrict__ bg,
    float* __restrict__ out)
{
    __shared__ float sc[4];
    const int t = threadIdx.x;
    const int b0 = blockIdx.x * 4;

    if (t < 4) {
        const int b = b0 + t;
        const float* e0 = g_e0 + (size_t)b * NEXP;
        float lg[NEXP];
#pragma unroll
        for (int e = 0; e < NEXP; e++) {
            float s = 0.f;
#pragma unroll
            for (int p = 0; p < GK_SPLIT; p++)
                s += g_logit_part[((size_t)p * B_ROWS + b) * NEXP + e];
            lg[e] = s;
        }
        float c = 1.f;
#pragma unroll
        for (int l = 0; l < L_LAYERS; l++) {
            const int base = l * E_EXP;
            float logit[E_EXP], mx = -1e30f;
#pragma unroll
            for (int e = 0; e < E_EXP; e++) {
                logit[e] = c * lg[base + e] + bg[base + e];
                mx = fmaxf(mx, logit[e]);
            }
            float se = 0.f, acc = 0.f;
#pragma unroll
            for (int e = 0; e < E_EXP; e++) {
                const float ge = expf(logit[e] - mx);
                se += ge;
                acc += ge * e0[base + e];
            }
            c += c * c * (acc / se);
        }
        sc[t] = c;
    }
    __syncthreads();

    const size_t base4 = (size_t)b0 * (D_DIM / 4);
    const float4* x4 = reinterpret_cast<const float4*>(X0) + base4;
    float4* o4 = reinterpret_cast<float4*>(out) + base4;
#pragma unroll
    for (int i = 0; i < 8; i++) {
        const int j = i * 256 + t;
        const float c = sc[j >> 9];
        float4 x = x4[j];
        x.x *= c; x.y *= c; x.z *= c; x.w *= c;
        o4[j] = x;
    }
}

// ---------------------------------------------------------------------------
// Launch: 3 kernels total. Gate logits live inside the GEMM launch.
// ---------------------------------------------------------------------------
extern "C" void kernel_launch(void* const* d_in, const int* in_sizes, int n_in,
                              void* d_out, int out_size) {
    const float* X0 = (const float*)d_in[0];
    const float* U  = (const float*)d_in[1];
    const float* V  = (const float*)d_in[2];
    const float* Wg = (const float*)d_in[3];
    const float* bg = (const float*)d_in[4];
    float* out = (float*)d_out;

    cudaFuncSetAttribute(gemm_hmma, cudaFuncAttributeMaxDynamicSharedMemorySize,
                         SMEM_TOTAL);

    prep_stream<<<PREP_TOTAL, 256>>>(U, V, X0);
    gemm_hmma<<<dim3(NEXP + GK_SPLIT, B_ROWS / BM), 128, SMEM_TOTAL>>>(X0, Wg);
    finalize<<<B_ROWS / 4, 256>>>(X0, bg, out);
}